// round 1
// baseline (speedup 1.0000x reference)
#include <cuda_runtime.h>
#include <cstdint>

// Device-global accumulators (no allocation allowed in kernel_launch).
__device__ float g_loss_sum;
__device__ unsigned long long g_nonzero_count;

__global__ void dlwm_init_kernel() {
    g_loss_sum = 0.0f;
    g_nonzero_count = 0ull;
}

__global__ void __launch_bounds__(256) dlwm_reduce_kernel(
    const float4* __restrict__ out,
    const float4* __restrict__ lbl0,
    const float4* __restrict__ lbl1,
    int n4)
{
    float acc = 0.0f;
    unsigned int cnt = 0;

    const int stride = gridDim.x * blockDim.x;
    int i = blockIdx.x * blockDim.x + threadIdx.x;

    // Unrolled grid-stride loop: 2 float4 triplets per iteration for deeper MLP.
    for (; i + stride < n4; i += 2 * stride) {
        float4 o0 = __ldg(out  + i);
        float4 a0 = __ldg(lbl0 + i);
        float4 b0 = __ldg(lbl1 + i);
        float4 o1 = __ldg(out  + i + stride);
        float4 a1 = __ldg(lbl0 + i + stride);
        float4 b1 = __ldg(lbl1 + i + stride);

        acc += fabsf(o0.x - a0.x) * b0.x;
        acc += fabsf(o0.y - a0.y) * b0.y;
        acc += fabsf(o0.z - a0.z) * b0.z;
        acc += fabsf(o0.w - a0.w) * b0.w;
        acc += fabsf(o1.x - a1.x) * b1.x;
        acc += fabsf(o1.y - a1.y) * b1.y;
        acc += fabsf(o1.z - a1.z) * b1.z;
        acc += fabsf(o1.w - a1.w) * b1.w;

        cnt += (a0.x != 0.0f) + (a0.y != 0.0f) + (a0.z != 0.0f) + (a0.w != 0.0f);
        cnt += (a1.x != 0.0f) + (a1.y != 0.0f) + (a1.z != 0.0f) + (a1.w != 0.0f);
    }
    // Tail (at most one stride worth)
    for (; i < n4; i += stride) {
        float4 o = __ldg(out  + i);
        float4 a = __ldg(lbl0 + i);
        float4 b = __ldg(lbl1 + i);
        acc += fabsf(o.x - a.x) * b.x;
        acc += fabsf(o.y - a.y) * b.y;
        acc += fabsf(o.z - a.z) * b.z;
        acc += fabsf(o.w - a.w) * b.w;
        cnt += (a.x != 0.0f) + (a.y != 0.0f) + (a.z != 0.0f) + (a.w != 0.0f);
    }

    // Warp reduce
    #pragma unroll
    for (int off = 16; off > 0; off >>= 1) {
        acc += __shfl_down_sync(0xFFFFFFFFu, acc, off);
        cnt += __shfl_down_sync(0xFFFFFFFFu, cnt, off);
    }

    // Block reduce via shared memory
    __shared__ float  s_acc[8];
    __shared__ unsigned int s_cnt[8];
    const int lane = threadIdx.x & 31;
    const int wid  = threadIdx.x >> 5;
    if (lane == 0) { s_acc[wid] = acc; s_cnt[wid] = cnt; }
    __syncthreads();

    if (wid == 0) {
        acc = (lane < (blockDim.x >> 5)) ? s_acc[lane] : 0.0f;
        cnt = (lane < (blockDim.x >> 5)) ? s_cnt[lane] : 0u;
        #pragma unroll
        for (int off = 4; off > 0; off >>= 1) {
            acc += __shfl_down_sync(0xFFFFFFFFu, acc, off);
            cnt += __shfl_down_sync(0xFFFFFFFFu, cnt, off);
        }
        if (lane == 0) {
            atomicAdd(&g_loss_sum, acc);
            atomicAdd(&g_nonzero_count, (unsigned long long)cnt);
        }
    }
}

__global__ void dlwm_finalize_kernel(float* __restrict__ d_out) {
    unsigned long long c = g_nonzero_count;
    d_out[0] = (c == 0ull) ? 0.0f : (g_loss_sum / (float)c);
}

extern "C" void kernel_launch(void* const* d_in, const int* in_sizes, int n_in,
                              void* d_out, int out_size)
{
    const float4* out_t = (const float4*)d_in[0];
    const float4* lbl0  = (const float4*)d_in[1];
    const float4* lbl1  = (const float4*)d_in[2];
    const int n  = in_sizes[0];        // 15,728,640 — divisible by 4
    const int n4 = n >> 2;

    const int threads = 256;
    // 148 SMs * 16 blocks/SM — grid-stride with ~5 double-iterations/thread.
    int blocks = 148 * 16;
    int max_blocks = (n4 + threads - 1) / threads;
    if (blocks > max_blocks) blocks = max_blocks;

    dlwm_init_kernel<<<1, 1>>>();
    dlwm_reduce_kernel<<<blocks, threads>>>(out_t, lbl0, lbl1, n4);
    dlwm_finalize_kernel<<<1, 1>>>((float*)d_out);
}